// round 14
// baseline (speedup 1.0000x reference)
#include <cuda_runtime.h>
#include <cstdint>

// Problem constants (fixed by the dataset)
#define BVAL   2048
#define TVAL   2048
#define HVAL   64
#define NBW    2                    // batches per warp
#define WARPS  4                    // warps per CTA
#define BTILE  (NBW * WARPS)        // 8 batches per CTA
#define THREADS (WARPS * 32)        // 128 threads
#define GRID   (BVAL / BTILE)       // 256 CTAs, 2/SM resident

#define TANH_C 2.885390082f         // 2*log2(e); folded into weights/bias

// ---------- packed f32x2 helpers (Blackwell) ----------
__device__ __forceinline__ unsigned long long ffma2(unsigned long long a,
                                                    unsigned long long b,
                                                    unsigned long long c) {
    unsigned long long d;
    asm("fma.rn.f32x2 %0, %1, %2, %3;" : "=l"(d) : "l"(a), "l"(b), "l"(c));
    return d;
}
__device__ __forceinline__ unsigned long long fadd2(unsigned long long a,
                                                    unsigned long long b) {
    unsigned long long d;
    asm("add.rn.f32x2 %0, %1, %2;" : "=l"(d) : "l"(a), "l"(b));
    return d;
}
__device__ __forceinline__ float lo32(unsigned long long v) {
    return __uint_as_float((unsigned)v);
}
__device__ __forceinline__ float hi32(unsigned long long v) {
    return __uint_as_float((unsigned)(v >> 32));
}
__device__ __forceinline__ unsigned long long pack2(float lo, float hi) {
    return (unsigned long long)__float_as_uint(lo) |
           ((unsigned long long)__float_as_uint(hi) << 32);
}

// tanh from PRE-SCALED input z = 2*log2(e)*s: tanh = 1 - 2/(ex2(z)+1).
// No clamp needed: z->+inf gives ex2->inf, rcp->0, result 1 exactly;
// z->-inf gives ex2->0, rcp(1)=1, result -1 exactly. rel err ~1e-7/step.
__device__ __forceinline__ float tanh_scaled(float z) {
    float p; asm("ex2.approx.f32 %0, %1;" : "=f"(p) : "f"(z));
    float r; asm("rcp.approx.f32 %0, %1;" : "=f"(r) : "f"(p + 1.0f));
    return fmaf(-2.0f, r, 1.0f);
}

__global__ void __launch_bounds__(THREADS, 2)
rnn_kernel(const float* __restrict__ x,     // [B,T,2]
           const float* __restrict__ W_ih,  // [64,2]
           const float* __restrict__ W_hh,  // [64,64]
           const float* __restrict__ b_ih,  // [64]
           const float* __restrict__ b_hh,  // [64]
           const float* __restrict__ W_fc,  // [2,64]
           const float* __restrict__ b_fc,  // [2]
           float* __restrict__ out)         // [B,2]
{
    // double-buffered hidden state, batch-major. Each warp owns 2 batches;
    // no cross-warp synchronization needed after this point.
    __shared__ __align__(16) float hbuf[2][BTILE][HVAL];

    const int tid  = threadIdx.x;
    const int lane = tid & 31;
    const int w    = tid >> 5;          // warp 0..3
    const int bid  = blockIdx.x;
    const int j0   = lane;              // first output row this thread owns
    const int j1   = lane + 32;         // second output row
    const int bl0  = NBW * w;           // first local batch of this warp
    const int b0   = bid * BTILE + bl0;

    // W_hh rows j0 and j1, k-packed into 32 u64 registers each, PRE-SCALED
    // by TANH_C (128 regs total, shared across both batches)
    unsigned long long wA[HVAL / 2], wB[HVAL / 2];
    {
        const float2* ra = reinterpret_cast<const float2*>(W_hh + j0 * HVAL);
        const float2* rb = reinterpret_cast<const float2*>(W_hh + j1 * HVAL);
        #pragma unroll
        for (int k = 0; k < HVAL / 2; k++) {
            float2 a = ra[k], b = rb[k];
            wA[k] = pack2(a.x * TANH_C, a.y * TANH_C);
            wB[k] = pack2(b.x * TANH_C, b.y * TANH_C);
        }
    }
    const float wihA0 = W_ih[2 * j0] * TANH_C, wihA1 = W_ih[2 * j0 + 1] * TANH_C;
    const float wihB0 = W_ih[2 * j1] * TANH_C, wihB1 = W_ih[2 * j1 + 1] * TANH_C;
    const float biasA = (b_ih[j0] + b_hh[j0]) * TANH_C;
    const float biasB = (b_ih[j1] + b_hh[j1]) * TANH_C;

    // h0 = 0 for both batches (each lane initializes its own 2 rows)
    hbuf[0][bl0 + 0][j0] = 0.0f;  hbuf[0][bl0 + 0][j1] = 0.0f;
    hbuf[0][bl0 + 1][j0] = 0.0f;  hbuf[0][bl0 + 1][j1] = 0.0f;
    __syncwarp();

    // ---- ANTI-PHASE SKEW. The two co-resident warps per SMSP are warp i of
    // CTA bid and of CTA bid+148 (classic bid->smid LUT repeats mod 148).
    // Their MAC bursts (~256 cyc fma demand) and serial tails (~240 cyc:
    // hadd->tanh->STS->smem-visible->LDS->chain refill) lockstep when in
    // phase, serializing the SMSP (step ~= 980 cyc, fma 50%). Give the
    // second-wave CTA a HALF-STEP (~512 cyc = 128 serial 4-cyc FFMA2 links)
    // head-start delay so one warp's MAC covers the other's tail. Warp
    // parity adds +-64 cyc to stagger LDS bursts across SMSPs.
    {
        const int links = 16 * (w & 1) + 128 * (bid >= 148 ? 1 : 0);
        if (links) {
            unsigned long long d0 = wA[0];
            #pragma unroll 1
            for (int k = 0; k < links; k++)
                d0 = ffma2(d0, wA[k & 31], d0);   // serial dependent chain
            if (biasA > 1.0e37f)   // never true for this model's data
                hbuf[0][bl0][j0] = lo32(d0);
        }
    }

    // x streams: one float4 = two timesteps, per batch (warp-uniform address)
    const float4* xq0 = reinterpret_cast<const float4*>(x + (size_t)(b0 + 0) * TVAL * 2);
    const float4* xq1 = reinterpret_cast<const float4*>(x + (size_t)(b0 + 1) * TVAL * 2);
    float4 c0 = xq0[0];
    float4 c1 = xq1[0];

    // one RNN step for both batches: read hbuf[RB], write hbuf[WB].
    // Batches interleaved at instruction level (proven best in R6).
    #define RNN_STEP(RB, WB, XA0, XB0, XA1, XB1)                                 \
    {                                                                            \
        float baseA0 = fmaf((XA0), wihA0, fmaf((XB0), wihA1, biasA));            \
        float baseB0 = fmaf((XA0), wihB0, fmaf((XB0), wihB1, biasB));            \
        float baseA1 = fmaf((XA1), wihA0, fmaf((XB1), wihA1, biasA));            \
        float baseB1 = fmaf((XA1), wihB0, fmaf((XB1), wihB1, biasB));            \
        unsigned long long aA0 = pack2(baseA0, 0.0f), aA0b = 0ull;               \
        unsigned long long aB0 = pack2(baseB0, 0.0f), aB0b = 0ull;               \
        unsigned long long aA1 = pack2(baseA1, 0.0f), aA1b = 0ull;               \
        unsigned long long aB1 = pack2(baseB1, 0.0f), aB1b = 0ull;               \
        const ulonglong2* hp0 =                                                  \
            reinterpret_cast<const ulonglong2*>(&hbuf[(RB)][bl0 + 0][0]);        \
        const ulonglong2* hp1 =                                                  \
            reinterpret_cast<const ulonglong2*>(&hbuf[(RB)][bl0 + 1][0]);        \
        _Pragma("unroll")                                                        \
        for (int kk = 0; kk < HVAL / 4; kk++) {                                  \
            ulonglong2 hv0 = hp0[kk];          /* LDS.128, broadcast */          \
            ulonglong2 hv1 = hp1[kk];                                            \
            aA0  = ffma2(hv0.x, wA[2 * kk],     aA0);                            \
            aA0b = ffma2(hv0.y, wA[2 * kk + 1], aA0b);                           \
            aB0  = ffma2(hv0.x, wB[2 * kk],     aB0);                            \
            aB0b = ffma2(hv0.y, wB[2 * kk + 1], aB0b);                           \
            aA1  = ffma2(hv1.x, wA[2 * kk],     aA1);                            \
            aA1b = ffma2(hv1.y, wA[2 * kk + 1], aA1b);                           \
            aB1  = ffma2(hv1.x, wB[2 * kk],     aB1);                            \
            aB1b = ffma2(hv1.y, wB[2 * kk + 1], aB1b);                           \
        }                                                                        \
        unsigned long long sA0 = fadd2(aA0, aA0b);                               \
        unsigned long long sB0 = fadd2(aB0, aB0b);                               \
        unsigned long long sA1 = fadd2(aA1, aA1b);                               \
        unsigned long long sB1 = fadd2(aB1, aB1b);                               \
        hbuf[(WB)][bl0 + 0][j0] = tanh_scaled(lo32(sA0) + hi32(sA0));            \
        hbuf[(WB)][bl0 + 0][j1] = tanh_scaled(lo32(sB0) + hi32(sB0));            \
        hbuf[(WB)][bl0 + 1][j0] = tanh_scaled(lo32(sA1) + hi32(sA1));            \
        hbuf[(WB)][bl0 + 1][j1] = tanh_scaled(lo32(sB1) + hi32(sB1));            \
        __syncwarp();                                                            \
    }

    #pragma unroll 1
    for (int t = 0; t < TVAL; t += 2) {
        // prefetch next pair of timesteps (clamped on the last iteration)
        int tn = (t + 2 < TVAL) ? (t / 2 + 1) : (TVAL / 2 - 1);
        float4 n0 = xq0[tn];
        float4 n1 = xq1[tn];
        RNN_STEP(0, 1, c0.x, c0.y, c1.x, c1.y)
        RNN_STEP(1, 0, c0.z, c0.w, c1.z, c1.w)
        c0 = n0;
        c1 = n1;
    }
    #undef RNN_STEP

    // Final FC on h_T (in hbuf[0] after an even number of steps).
    // O=2, 2 batches per warp: lanes 0..3 cover (batch, output) combos.
    if (lane < 4) {
        const int which = lane >> 1;       // batch within warp pair
        const int oj    = lane & 1;        // output index 0/1
        const float* hv  = &hbuf[0][bl0 + which][0];
        const float* wfc = W_fc + oj * HVAL;
        float acc = b_fc[oj];
        #pragma unroll
        for (int k = 0; k < HVAL; k++)
            acc = fmaf(hv[k], wfc[k], acc);
        out[(b0 + which) * 2 + oj] = acc;
    }
}

extern "C" void kernel_launch(void* const* d_in, const int* in_sizes, int n_in,
                              void* d_out, int out_size) {
    const float* x    = (const float*)d_in[0];
    const float* W_ih = (const float*)d_in[1];
    const float* W_hh = (const float*)d_in[2];
    const float* b_ih = (const float*)d_in[3];
    const float* b_hh = (const float*)d_in[4];
    const float* W_fc = (const float*)d_in[5];
    const float* b_fc = (const float*)d_in[6];
    rnn_kernel<<<GRID, THREADS>>>(x, W_ih, W_hh, b_ih, b_hh,
                                  W_fc, b_fc, (float*)d_out);
}

// round 15
// speedup vs baseline: 1.1046x; 1.1046x over previous
#include <cuda_runtime.h>
#include <cstdint>

// Problem constants (fixed by the dataset)
#define BVAL   2048
#define TVAL   2048
#define HVAL   64
#define NBW    2                    // batches per warp
#define WARPS  4                    // warps per CTA
#define BTILE  (NBW * WARPS)        // 8 batches per CTA
#define THREADS (WARPS * 32)        // 128 threads
#define GRID   (BVAL / BTILE)       // 256 CTAs, 2/SM resident

// ---------- packed f32x2 helpers (Blackwell) ----------
__device__ __forceinline__ unsigned long long ffma2(unsigned long long a,
                                                    unsigned long long b,
                                                    unsigned long long c) {
    unsigned long long d;
    asm("fma.rn.f32x2 %0, %1, %2, %3;" : "=l"(d) : "l"(a), "l"(b), "l"(c));
    return d;
}
__device__ __forceinline__ unsigned long long fadd2(unsigned long long a,
                                                    unsigned long long b) {
    unsigned long long d;
    asm("add.rn.f32x2 %0, %1, %2;" : "=l"(d) : "l"(a), "l"(b));
    return d;
}
__device__ __forceinline__ float lo32(unsigned long long v) {
    return __uint_as_float((unsigned)v);
}
__device__ __forceinline__ float hi32(unsigned long long v) {
    return __uint_as_float((unsigned)(v >> 32));
}
__device__ __forceinline__ unsigned long long pack2(float lo, float hi) {
    return (unsigned long long)__float_as_uint(lo) |
           ((unsigned long long)__float_as_uint(hi) << 32);
}

// Single-op MUFU tanh (Turing+). Worst-case rel err ~5e-4 per application;
// the RNN recurrence is contractive (||W_hh|| ~ 0.6, |tanh'| <= 1) so the
// error reaches a small fixed point (~1e-4) instead of accumulating.
__device__ __forceinline__ float fast_tanh(float s) {
    float t;
    asm("tanh.approx.f32 %0, %1;" : "=f"(t) : "f"(s));
    return t;
}

__global__ void __launch_bounds__(THREADS, 2)
rnn_kernel(const float* __restrict__ x,     // [B,T,2]
           const float* __restrict__ W_ih,  // [64,2]
           const float* __restrict__ W_hh,  // [64,64]
           const float* __restrict__ b_ih,  // [64]
           const float* __restrict__ b_hh,  // [64]
           const float* __restrict__ W_fc,  // [2,64]
           const float* __restrict__ b_fc,  // [2]
           float* __restrict__ out)         // [B,2]
{
    // double-buffered hidden state, batch-major. Each warp owns 2 batches;
    // no cross-warp synchronization needed after this point.
    __shared__ __align__(16) float hbuf[2][BTILE][HVAL];

    const int tid  = threadIdx.x;
    const int lane = tid & 31;
    const int w    = tid >> 5;          // warp 0..3
    const int bid  = blockIdx.x;
    const int j0   = lane;              // first output row this thread owns
    const int j1   = lane + 32;         // second output row
    const int bl0  = NBW * w;           // first local batch of this warp
    const int b0   = bid * BTILE + bl0;

    // W_hh rows j0 and j1, k-packed into 32 u64 registers each
    // (128 regs total, shared across both batches). No pre-scaling:
    // tanh.approx takes the raw pre-activation.
    unsigned long long wA[HVAL / 2], wB[HVAL / 2];
    {
        const unsigned long long* ra =
            reinterpret_cast<const unsigned long long*>(W_hh + j0 * HVAL);
        const unsigned long long* rb =
            reinterpret_cast<const unsigned long long*>(W_hh + j1 * HVAL);
        #pragma unroll
        for (int k = 0; k < HVAL / 2; k++) { wA[k] = ra[k]; wB[k] = rb[k]; }
    }
    const float wihA0 = W_ih[2 * j0], wihA1 = W_ih[2 * j0 + 1];
    const float wihB0 = W_ih[2 * j1], wihB1 = W_ih[2 * j1 + 1];
    const float biasA = b_ih[j0] + b_hh[j0];
    const float biasB = b_ih[j1] + b_hh[j1];

    // h0 = 0 for both batches (each lane initializes its own 2 rows)
    hbuf[0][bl0 + 0][j0] = 0.0f;  hbuf[0][bl0 + 0][j1] = 0.0f;
    hbuf[0][bl0 + 1][j0] = 0.0f;  hbuf[0][bl0 + 1][j1] = 0.0f;
    __syncwarp();

    // ---- GRADED PHASE SKEW (proven R12 winner, unchanged). 4 phases:
    //   warp-parity bit -> desyncs LDS bursts across SMSPs (shared L1)
    //   CTA-wave bit    -> desyncs co-resident warps per SMSP
    // Each phase unit = dependent chain of 16 FFMA2 (~64 cyc).
    {
        const int phase = (w & 1) + ((bid >= 148) ? 2 : 0);
        if (phase) {
            unsigned long long d0 = wA[0];
            const int n = phase * 16;
            #pragma unroll 1
            for (int k = 0; k < n; k++)
                d0 = ffma2(d0, wA[k & 31], d0);   // serial: 4 cyc/link
            if (biasA > 1.0e37f)   // never true for this model's data
                hbuf[0][bl0][j0] = lo32(d0);
        }
    }

    // x streams: one float4 = two timesteps, per batch (warp-uniform address)
    const float4* xq0 = reinterpret_cast<const float4*>(x + (size_t)(b0 + 0) * TVAL * 2);
    const float4* xq1 = reinterpret_cast<const float4*>(x + (size_t)(b0 + 1) * TVAL * 2);
    float4 c0 = xq0[0];
    float4 c1 = xq1[0];

    // one RNN step for both batches: read hbuf[RB], write hbuf[WB].
    // Batches interleaved at instruction level (proven best in R6).
    #define RNN_STEP(RB, WB, XA0, XB0, XA1, XB1)                                 \
    {                                                                            \
        float baseA0 = fmaf((XA0), wihA0, fmaf((XB0), wihA1, biasA));            \
        float baseB0 = fmaf((XA0), wihB0, fmaf((XB0), wihB1, biasB));            \
        float baseA1 = fmaf((XA1), wihA0, fmaf((XB1), wihA1, biasA));            \
        float baseB1 = fmaf((XA1), wihB0, fmaf((XB1), wihB1, biasB));            \
        unsigned long long aA0 = pack2(baseA0, 0.0f), aA0b = 0ull;               \
        unsigned long long aB0 = pack2(baseB0, 0.0f), aB0b = 0ull;               \
        unsigned long long aA1 = pack2(baseA1, 0.0f), aA1b = 0ull;               \
        unsigned long long aB1 = pack2(baseB1, 0.0f), aB1b = 0ull;               \
        const ulonglong2* hp0 =                                                  \
            reinterpret_cast<const ulonglong2*>(&hbuf[(RB)][bl0 + 0][0]);        \
        const ulonglong2* hp1 =                                                  \
            reinterpret_cast<const ulonglong2*>(&hbuf[(RB)][bl0 + 1][0]);        \
        _Pragma("unroll")                                                        \
        for (int kk = 0; kk < HVAL / 4; kk++) {                                  \
            ulonglong2 hv0 = hp0[kk];          /* LDS.128, broadcast */          \
            ulonglong2 hv1 = hp1[kk];                                            \
            aA0  = ffma2(hv0.x, wA[2 * kk],     aA0);                            \
            aA0b = ffma2(hv0.y, wA[2 * kk + 1], aA0b);                           \
            aB0  = ffma2(hv0.x, wB[2 * kk],     aB0);                            \
            aB0b = ffma2(hv0.y, wB[2 * kk + 1], aB0b);                           \
            aA1  = ffma2(hv1.x, wA[2 * kk],     aA1);                            \
            aA1b = ffma2(hv1.y, wA[2 * kk + 1], aA1b);                           \
            aB1  = ffma2(hv1.x, wB[2 * kk],     aB1);                            \
            aB1b = ffma2(hv1.y, wB[2 * kk + 1], aB1b);                           \
        }                                                                        \
        unsigned long long sA0 = fadd2(aA0, aA0b);                               \
        unsigned long long sB0 = fadd2(aB0, aB0b);                               \
        unsigned long long sA1 = fadd2(aA1, aA1b);                               \
        unsigned long long sB1 = fadd2(aB1, aB1b);                               \
        hbuf[(WB)][bl0 + 0][j0] = fast_tanh(lo32(sA0) + hi32(sA0));              \
        hbuf[(WB)][bl0 + 0][j1] = fast_tanh(lo32(sB0) + hi32(sB0));              \
        hbuf[(WB)][bl0 + 1][j0] = fast_tanh(lo32(sA1) + hi32(sA1));              \
        hbuf[(WB)][bl0 + 1][j1] = fast_tanh(lo32(sB1) + hi32(sB1));              \
        __syncwarp();                                                            \
    }

    #pragma unroll 1
    for (int t = 0; t < TVAL; t += 2) {
        // prefetch next pair of timesteps (clamped on the last iteration)
        int tn = (t + 2 < TVAL) ? (t / 2 + 1) : (TVAL / 2 - 1);
        float4 n0 = xq0[tn];
        float4 n1 = xq1[tn];
        RNN_STEP(0, 1, c0.x, c0.y, c1.x, c1.y)
        RNN_STEP(1, 0, c0.z, c0.w, c1.z, c1.w)
        c0 = n0;
        c1 = n1;
    }
    #undef RNN_STEP

    // Final FC on h_T (in hbuf[0] after an even number of steps).
    // O=2, 2 batches per warp: lanes 0..3 cover (batch, output) combos.
    if (lane < 4) {
        const int which = lane >> 1;       // batch within warp pair
        const int oj    = lane & 1;        // output index 0/1
        const float* hv  = &hbuf[0][bl0 + which][0];
        const float* wfc = W_fc + oj * HVAL;
        float acc = b_fc[oj];
        #pragma unroll
        for (int k = 0; k < HVAL; k++)
            acc = fmaf(hv[k], wfc[k], acc);
        out[(b0 + which) * 2 + oj] = acc;
    }
}

extern "C" void kernel_launch(void* const* d_in, const int* in_sizes, int n_in,
                              void* d_out, int out_size) {
    const float* x    = (const float*)d_in[0];
    const float* W_ih = (const float*)d_in[1];
    const float* W_hh = (const float*)d_in[2];
    const float* b_ih = (const float*)d_in[3];
    const float* b_hh = (const float*)d_in[4];
    const float* W_fc = (const float*)d_in[5];
    const float* b_fc = (const float*)d_in[6];
    rnn_kernel<<<GRID, THREADS>>>(x, W_ih, W_hh, b_ih, b_hh,
                                  W_fc, b_fc, (float*)d_out);
}